// round 4
// baseline (speedup 1.0000x reference)
#include <cuda_runtime.h>

#define T_DATA 20000
#define E_NO   2000
#define I_NO   500
#define NSUB   12
#define T_SYN  200
#define TPAD   20512
#define TOFF   256
#define WE     63      // ceil(2000/32)
#define WI     16      // ceil(500/32)

// ---------------- device scratch (no allocations allowed) ----------------
__device__ float    g_IN  [24 * TPAD];     // rows 0..11 = IN_e, 12..23 = IN_i, col = TOFF + t
__device__ float    g_SYN [24 * TPAD];     // rows 0..11 = syn_s, 12..23 = syn_ns
__device__ unsigned g_PACKE[WE * T_DATA];  // [w][t]
__device__ unsigned g_PACKI[WI * T_DATA];
__device__ unsigned g_CTBE[NSUB * WE];
__device__ unsigned g_CTBI[NSUB * WI];
__device__ float    g_KER [4 * NSUB * T_SYN];  // pc: 0=(s,e) 1=(s,i) 2=(ns,e) 3=(ns,i)

__device__ __forceinline__ float sigmoidf_(float x) {
    return 1.0f / (1.0f + __expf(-x));
}

// ---------------- K0: zero pads, build syn kernels, bit-pack C ----------------
__global__ void k0_prep(const float* __restrict__ Ce, const float* __restrict__ Ci,
                        const float* __restrict__ Wss, const float* __restrict__ Wns,
                        const float* __restrict__ Dss, const float* __restrict__ Dns) {
    int gid = blockIdx.x * 256 + threadIdx.x;
    if (gid < 18432) {
        int region = gid / 6144, e = gid % 6144;
        int row = e >> 8, col = e & 255;
        if (region == 0)      g_IN [row * TPAD + col] = 0.f;
        else if (region == 1) g_IN [row * TPAD + TOFF + T_DATA + col] = 0.f;
        else                  g_SYN[row * TPAD + col] = 0.f;
    } else if (gid < 28032) {
        int j = gid - 18432;
        int t = j % 200;
        int s = (j / 200) % 12;
        int pc = j / 2400;         // 0..3
        int p = pc >> 1, c = pc & 1;
        const float* W = p ? Wns : Wss;
        const float* D = p ? Dns : Dss;
        float d  = expf(D[s * 2 + c]);
        float ts = fmaxf((float)t - d, 0.f);
        float acc = 0.f;
        #pragma unroll
        for (int b = 0; b < 3; ++b) {
            float tau = expf(0.5f * (float)b);
            float tt  = ts / tau;
            acc += W[s * 6 + b * 2 + c] * tt * expf(-tt);
        }
        g_KER[(pc * 12 + s) * 200 + t] = acc;
    } else if (gid < 28788) {
        int j = gid - 28032;
        int s = j / WE, w = j % WE;
        unsigned m = 0;
        for (int b = 0; b < 32; ++b) {
            int k = w * 32 + b;
            if (k < E_NO && Ce[s * E_NO + k] != 0.f) m |= (1u << b);
        }
        g_CTBE[s * WE + w] = m;
    } else if (gid < 28980) {
        int j = gid - 28788;
        int s = j / WI, w = j % WI;
        unsigned m = 0;
        for (int b = 0; b < 32; ++b) {
            int k = w * 32 + b;
            if (k < I_NO && Ci[s * I_NO + k] != 0.f) m |= (1u << b);
        }
        g_CTBI[s * WI + w] = m;
    }
}

// ---------------- K1: bit-pack spike matrices (DRAM-bound, 200 MB) ----------------
__global__ void __launch_bounds__(256) k1_pack(const float* __restrict__ Se,
                                               const float* __restrict__ Si) {
    int wid  = (blockIdx.x * 256 + threadIdx.x) >> 5;   // one warp per time row
    int lane = threadIdx.x & 31;
    if (wid >= T_DATA) return;
    const float* rowE = Se + (size_t)wid * E_NO;
    const float* rowI = Si + (size_t)wid * I_NO;
    #pragma unroll 4
    for (int w = 0; w < WE; ++w) {
        int k = w * 32 + lane;
        float v = (k < E_NO) ? rowE[k] : 0.f;
        unsigned m = __ballot_sync(0xffffffffu, v != 0.f);
        if (lane == 0) g_PACKE[w * T_DATA + wid] = m;
    }
    #pragma unroll 4
    for (int w = 0; w < WI; ++w) {
        int k = w * 32 + lane;
        float v = (k < I_NO) ? rowI[k] : 0.f;
        unsigned m = __ballot_sync(0xffffffffu, v != 0.f);
        if (lane == 0) g_PACKI[w * T_DATA + wid] = m;
    }
}

// ---------------- K2: popcount "GEMM" -> IN (exact integers) ----------------
__global__ void __launch_bounds__(256) k2_popc() {
    __shared__ unsigned se[NSUB * WE];
    __shared__ unsigned si[NSUB * WI];
    int tid = threadIdx.x;
    for (int i = tid; i < NSUB * WE; i += 256) se[i] = g_CTBE[i];
    for (int i = tid; i < NSUB * WI; i += 256) si[i] = g_CTBI[i];
    __syncthreads();
    int t = blockIdx.x * 256 + tid;
    if (t >= T_DATA) return;
    int acce[12], acci[12];
    #pragma unroll
    for (int s = 0; s < 12; ++s) { acce[s] = 0; acci[s] = 0; }
    for (int w = 0; w < WE; ++w) {
        unsigned sw = g_PACKE[w * T_DATA + t];
        #pragma unroll
        for (int s = 0; s < 12; ++s) acce[s] += __popc(sw & se[s * WE + w]);
    }
    #pragma unroll
    for (int w = 0; w < WI; ++w) {
        unsigned sw = g_PACKI[w * T_DATA + t];
        #pragma unroll
        for (int s = 0; s < 12; ++s) acci[s] += __popc(sw & si[s * WI + w]);
    }
    #pragma unroll
    for (int s = 0; s < 12; ++s) {
        g_IN[s        * TPAD + TOFF + t] = (float)acce[s];
        g_IN[(12 + s) * TPAD + TOFF + t] = (float)acci[s];
    }
}

// ---------------- K3: 200-tap causal conv (warp per subunit, 256 t per block) ----
__global__ void __launch_bounds__(384) k3_conv() {
    __shared__ float sIN[24][456];
    int t0 = blockIdx.x * 256;
    int base = TOFF + t0 - 199;
    for (int i = threadIdx.x; i < 24 * 456; i += 384) {
        int c = i / 456, x = i % 456;
        sIN[c][x] = g_IN[c * TPAD + base + x];
    }
    __syncthreads();
    int s    = threadIdx.x / 32;       // 12 warps, one subunit each
    int lane = threadIdx.x & 31;
    float as[8], ans[8];
    #pragma unroll
    for (int r = 0; r < 8; ++r) { as[r] = 0.f; ans[r] = 0.f; }
    const float* kb = g_KER + s * 200;
    for (int k = 0; k < 200; ++k) {
        float kes = __ldg(kb + 0 * 2400 + k);
        float kis = __ldg(kb + 1 * 2400 + k);
        float ken = __ldg(kb + 2 * 2400 + k);
        float kin = __ldg(kb + 3 * 2400 + k);
        #pragma unroll
        for (int r = 0; r < 8; ++r) {
            int x = 199 - k + lane + 32 * r;
            float e  = sIN[s][x];
            float fi = sIN[12 + s][x];
            as [r] = fmaf(kes, e, fmaf(kis, fi, as [r]));
            ans[r] = fmaf(ken, e, fmaf(kin, fi, ans[r]));
        }
    }
    #pragma unroll
    for (int r = 0; r < 8; ++r) {
        int t = t0 + lane + 32 * r;
        if (t < T_DATA) {
            g_SYN[s        * TPAD + TOFF + t] = as [r];
            g_SYN[(12 + s) * TPAD + TOFF + t] = ans[r];
        }
    }
}

// ---------------- K4: "scan" as a 12-level feed-forward cascade ----------------
// C_den is strictly lower triangular -> Y[i](t) depends only on Y[j<i](t-1):
// levels are fully parallel over t; blocks are independent with a 12-step halo.
__global__ void __launch_bounds__(128) k4_scan(const float* __restrict__ Cden,
                                               const float* __restrict__ Ths,
                                               const float* __restrict__ Thns,
                                               const float* __restrict__ Wssub,
                                               const float* __restrict__ Wnssub,
                                               float* __restrict__ out) {
    __shared__ float xno[12][140];     // sigmoid(X_ns) per level; col h <-> t = t0-12+h
    __shared__ float cwns[144], cds[144];
    __shared__ float ths[12], thns[12], ws[12], wns[12];
    int tid = threadIdx.x;
    // NOTE: 144 > blockDim (128) -> MUST stride, not a single guarded store.
    for (int v = tid; v < 144; v += 128) {
        float c = Cden[v];
        cds [v] = c;
        cwns[v] = c * Wnssub[v % 12];
    }
    if (tid < 12) {
        ths [tid] = Ths[tid];
        thns[tid] = Thns[tid];
        ws  [tid] = Wssub[tid];
        wns [tid] = Wnssub[tid];
    }
    __syncthreads();
    int t0 = blockIdx.x * 128;

    #pragma unroll
    for (int i = 0; i < 12; ++i) {
        for (int h = tid; h < 140; h += 128) {
            int t = t0 - 12 + h;
            float v = 0.f;
            if (t >= 0 && t < T_DATA) {
                float x = g_SYN[(12 + i) * TPAD + TOFF + t] + thns[i];
                #pragma unroll
                for (int j = 0; j < i; ++j) {
                    float yp = (h > 0) ? xno[j][h - 1] : 0.f;
                    x = fmaf(cwns[i * 12 + j], yp, x);
                }
                v = sigmoidf_(x);
            }
            xno[i][h] = v;      // row i written, rows j<i read: no race
        }
        __syncthreads();
    }

    int t = t0 + tid;
    if (t < T_DATA) {
        int h = 12 + tid;
        float xt[12];
        #pragma unroll
        for (int i = 0; i < 12; ++i) xt[i] = xno[i][h];

        float ysp[12];
        if (t == 0) {
            #pragma unroll
            for (int j = 0; j < 12; ++j) ysp[j] = 0.f;
        } else {
            float x0 = g_SYN[0 * TPAD + TOFF + (t - 1)] + ths[0];
            ysp[0] = sigmoidf_(x0) * ws[0];
            #pragma unroll
            for (int j = 1; j < 12; ++j) ysp[j] = xno[j][h - 1] * ws[j];
        }

        float* o = out + (size_t)t * 35;
        #pragma unroll
        for (int i = 0; i < 12; ++i) {
            float xs = g_SYN[i * TPAD + TOFF + t] + ths[i];
            #pragma unroll
            for (int j = 0; j < i; ++j) xs = fmaf(cds[i * 12 + j], ysp[j], xs);
            float sg  = sigmoidf_(xs);
            float ysn = (i == 0) ? sg * ws[0] : xt[i] * ws[i];
            o[i]      = ysn;
            o[12 + i] = xt[i] * wns[i];
            if (i >= 1) o[24 + i - 1] = sg;
        }
    }
}

// ---------------- launch ----------------
extern "C" void kernel_launch(void* const* d_in, const int* in_sizes, int n_in,
                              void* d_out, int out_size) {
    const float* S_e      = (const float*)d_in[0];
    const float* S_i      = (const float*)d_in[1];
    const float* C_syn_e  = (const float*)d_in[2];
    const float* C_syn_i  = (const float*)d_in[3];
    const float* C_den    = (const float*)d_in[4];
    const float* W_s_syn  = (const float*)d_in[5];
    const float* W_ns_syn = (const float*)d_in[6];
    const float* D_s      = (const float*)d_in[7];
    const float* D_ns     = (const float*)d_in[8];
    const float* Theta_s  = (const float*)d_in[9];
    const float* Theta_ns = (const float*)d_in[10];
    const float* W_s_sub  = (const float*)d_in[11];
    const float* W_ns_sub = (const float*)d_in[12];
    float* out = (float*)d_out;

    k0_prep<<<114, 256>>>(C_syn_e, C_syn_i, W_s_syn, W_ns_syn, D_s, D_ns);
    k1_pack<<<2500, 256>>>(S_e, S_i);
    k2_popc<<<79, 256>>>();
    k3_conv<<<79, 384>>>();
    k4_scan<<<157, 128>>>(C_den, Theta_s, Theta_ns, W_s_sub, W_ns_sub, out);
}

// round 5
// speedup vs baseline: 1.9054x; 1.9054x over previous
#include <cuda_runtime.h>

#define T_DATA 20000
#define TOFF   256
#define TPAD   20512
#define NXI    (TOFF + T_DATA)     // 20256 rows in g_INT2

// ---------------- device scratch ----------------
__device__ float2   g_INT2[NXI * 12];    // [x][s] = (IN_e, IN_i), x = TOFF + t
__device__ float2   g_SYN2[12 * TPAD];   // [s][x] = (syn_s, syn_ns)
__device__ float4   g_KER4[12 * 200];    // (kes, kis, ken, kin) per (s,k)
__device__ unsigned g_CTBE[64 * 12];     // [wc][s]  wc = 4*w + c  (permuted bit layout)
__device__ unsigned g_CTBI[16 * 12];

__device__ __forceinline__ float sigmoidf_(float x) {
    return 1.0f / (1.0f + __expf(-x));
}

// ---------------- K0a: pack C_syn into permuted bitmasks ----------------
// bit l of word (wc, s) = C[s][128*(wc>>2) + 4*l + (wc&3)]  -- matches the
// float4-ballot permutation used in k1f. Any consistent permutation keeps the
// AND/POPC counts exact.
__global__ void k0a(const float* __restrict__ Ce, const float* __restrict__ Ci) {
    int gid = blockIdx.x * 256 + threadIdx.x;
    if (gid < 768) {
        int wc = gid / 12, s = gid % 12;
        unsigned m = 0;
        #pragma unroll 4
        for (int l = 0; l < 32; ++l) {
            int idx = 128 * (wc >> 2) + 4 * l + (wc & 3);
            if (idx < 2000 && Ce[s * 2000 + idx] != 0.f) m |= (1u << l);
        }
        g_CTBE[wc * 12 + s] = m;
    } else if (gid < 960) {
        int j = gid - 768;
        int wc = j / 12, s = j % 12;
        unsigned m = 0;
        #pragma unroll 4
        for (int l = 0; l < 32; ++l) {
            int idx = 128 * (wc >> 2) + 4 * l + (wc & 3);
            if (idx < 500 && Ci[s * 500 + idx] != 0.f) m |= (1u << l);
        }
        g_CTBI[wc * 12 + s] = m;
    }
}

// synaptic kernel coefficient for one (path, component, s, t)
__device__ __forceinline__ float coef1(const float* __restrict__ W,
                                       const float* __restrict__ D,
                                       int s, int c, float t) {
    float ts = fmaxf(t - expf(D[s * 2 + c]), 0.f);
    float acc = 0.f;
    #pragma unroll
    for (int b = 0; b < 3; ++b) {
        float tau = expf(0.5f * (float)b);
        float tt  = ts / tau;
        acc += W[s * 6 + b * 2 + c] * tt * expf(-tt);
    }
    return acc;
}

// ---------------- K1f: fused bit-pack + popcount GEMM (+prep side-blocks) ----
// Blocks [0,2500): one warp per time row. float4 loads -> 4 ballots -> popc
// against smem C-tables; lane s (<12) accumulates subunit s. The packed masks
// never touch DRAM. Blocks [2500,2534): build g_KER4 + zero pads (independent).
__global__ void __launch_bounds__(256) k1f(const float4* __restrict__ Se4,
                                           const float4* __restrict__ Si4,
                                           const float* __restrict__ Wss,
                                           const float* __restrict__ Wns,
                                           const float* __restrict__ Dss,
                                           const float* __restrict__ Dns) {
    if (blockIdx.x >= 2500) {
        int gid = (blockIdx.x - 2500) * 256 + threadIdx.x;
        if (gid < 2400) {
            int s = gid / 200, k = gid % 200;
            float t = (float)k;
            float4 o;
            o.x = coef1(Wss, Dss, s, 0, t);   // s-path, e
            o.y = coef1(Wss, Dss, s, 1, t);   // s-path, i
            o.z = coef1(Wns, Dns, s, 0, t);   // ns-path, e
            o.w = coef1(Wns, Dns, s, 1, t);   // ns-path, i
            g_KER4[gid] = o;                  // gid == s*200 + k
        } else if (gid < 5472) {
            g_INT2[gid - 2400] = make_float2(0.f, 0.f);       // x < 256, all s
        } else if (gid < 8544) {
            int j = gid - 5472;
            int s = j >> 8, x = j & 255;
            g_SYN2[s * TPAD + x] = make_float2(0.f, 0.f);
        }
        return;
    }
    __shared__ unsigned sCE[768], sCI[192];
    int tid = threadIdx.x;
    for (int i = tid; i < 768; i += 256) sCE[i] = g_CTBE[i];
    if (tid < 192) sCI[tid] = g_CTBI[tid];
    __syncthreads();

    int lane = tid & 31;
    int row  = blockIdx.x * 8 + (tid >> 5);          // time index t
    const float4* rE = Se4 + (size_t)row * 500;
    const float4* rI = Si4 + (size_t)row * 125;
    int lc = (lane < 12) ? lane : 0;
    int accE = 0, accI = 0;

    #pragma unroll
    for (int w = 0; w < 16; ++w) {
        int f = w * 32 + lane;
        float4 v = (f < 500) ? __ldg(rE + f) : make_float4(0.f, 0.f, 0.f, 0.f);
        unsigned m0 = __ballot_sync(0xffffffffu, v.x != 0.f);
        unsigned m1 = __ballot_sync(0xffffffffu, v.y != 0.f);
        unsigned m2 = __ballot_sync(0xffffffffu, v.z != 0.f);
        unsigned m3 = __ballot_sync(0xffffffffu, v.w != 0.f);
        int b = w * 48 + lc;
        accE += __popc(m0 & sCE[b]);
        accE += __popc(m1 & sCE[b + 12]);
        accE += __popc(m2 & sCE[b + 24]);
        accE += __popc(m3 & sCE[b + 36]);
    }
    #pragma unroll
    for (int w = 0; w < 4; ++w) {
        int f = w * 32 + lane;
        float4 v = (f < 125) ? __ldg(rI + f) : make_float4(0.f, 0.f, 0.f, 0.f);
        unsigned m0 = __ballot_sync(0xffffffffu, v.x != 0.f);
        unsigned m1 = __ballot_sync(0xffffffffu, v.y != 0.f);
        unsigned m2 = __ballot_sync(0xffffffffu, v.z != 0.f);
        unsigned m3 = __ballot_sync(0xffffffffu, v.w != 0.f);
        int b = w * 48 + lc;
        accI += __popc(m0 & sCI[b]);
        accI += __popc(m1 & sCI[b + 12]);
        accI += __popc(m2 & sCI[b + 24]);
        accI += __popc(m3 & sCI[b + 36]);
    }
    if (lane < 12)
        g_INT2[(TOFF + row) * 12 + lane] = make_float2((float)accE, (float)accI);
}

// ---------------- K3: 200-tap causal conv ----------------
// 125 blocks (one full wave) x 160 t. 24 warps: warp = (half, s); each warp
// convolves 100 taps for subunit s over 160 outputs (r=5), halves combined in
// smem. Data float2-interleaved (1 LDS.64 per 4 FMA), coefs float4 (1 LDG.128).
__global__ void __launch_bounds__(768) k3_conv() {
    __shared__ float2 sIN[12 * 360];      // [s][xx], xx = (t - t0) + 199 - k
    __shared__ float2 sP [12 * 160];      // partials from tap-half 1
    int tid = threadIdx.x;
    int t0  = blockIdx.x * 160;
    int baseflat = (TOFF + t0 - 199) * 12;
    for (int i = tid; i < 4308; i += 768) {         // 359 x-rows * 12 subunits
        int xx = i / 12, s = i % 12;
        sIN[s * 360 + xx] = g_INT2[baseflat + i];
    }
    __syncthreads();

    int warp = tid >> 5, lane = tid & 31;
    int s = warp % 12, half = warp / 12;
    float as[5], an[5];
    #pragma unroll
    for (int r = 0; r < 5; ++r) { as[r] = 0.f; an[r] = 0.f; }

    const float4* kp = g_KER4 + s * 200 + half * 100;
    const float2* dp = sIN + s * 360 + (199 - half * 100) + lane;
    #pragma unroll 2
    for (int kk = 0; kk < 100; ++kk) {
        float4 kc = __ldg(kp + kk);
        #pragma unroll
        for (int r = 0; r < 5; ++r) {
            float2 ei = dp[32 * r - kk];
            as[r] = fmaf(kc.x, ei.x, fmaf(kc.y, ei.y, as[r]));
            an[r] = fmaf(kc.z, ei.x, fmaf(kc.w, ei.y, an[r]));
        }
    }
    if (half == 1) {
        #pragma unroll
        for (int r = 0; r < 5; ++r)
            sP[s * 160 + lane + 32 * r] = make_float2(as[r], an[r]);
    }
    __syncthreads();
    if (half == 0) {
        #pragma unroll
        for (int r = 0; r < 5; ++r) {
            float2 p = sP[s * 160 + lane + 32 * r];
            g_SYN2[s * TPAD + TOFF + t0 + lane + 32 * r] =
                make_float2(as[r] + p.x, an[r] + p.y);
        }
    }
}

// ---------------- K4: 12-level feed-forward cascade + outputs ----------------
// C_den strictly lower-triangular -> level i at col h is exact for h >= i;
// halo 12 covers the deepest dependency. 125 blocks x 160 t, 192 threads.
__global__ void __launch_bounds__(192) k4_scan(const float* __restrict__ Cden,
                                               const float* __restrict__ Ths,
                                               const float* __restrict__ Thns,
                                               const float* __restrict__ Wssub,
                                               const float* __restrict__ Wnssub,
                                               float* __restrict__ out) {
    __shared__ float xno[12][176];       // sigmoid(X_ns); col h <-> t = t0-12+h
    __shared__ float sout[160 * 35];
    __shared__ float cwns[144], cds[144];
    __shared__ float ths[12], thns[12], ws[12], wns[12];
    int tid = threadIdx.x;
    if (tid < 144) {
        float c = Cden[tid];
        cds [tid] = c;
        cwns[tid] = c * Wnssub[tid % 12];
    }
    if (tid < 12) {
        ths [tid] = Ths[tid];
        thns[tid] = Thns[tid];
        ws  [tid] = Wssub[tid];
        wns [tid] = Wnssub[tid];
    }
    __syncthreads();
    int t0 = blockIdx.x * 160;

    #pragma unroll
    for (int i = 0; i < 12; ++i) {
        if (tid < 172) {
            int t = t0 - 12 + tid;
            float v = 0.f;
            if (t >= 0) {                          // t < T_DATA always holds
                float x = g_SYN2[i * TPAD + TOFF + t].y + thns[i];
                #pragma unroll
                for (int j = 0; j < i; ++j) {
                    float yp = (tid > 0) ? xno[j][tid - 1] : 0.f;
                    x = fmaf(cwns[i * 12 + j], yp, x);
                }
                v = sigmoidf_(x);
            }
            xno[i][tid] = v;
        }
        __syncthreads();
    }

    if (tid < 160) {
        int t = t0 + tid, h = 12 + tid;
        float ysp[12];
        if (t == 0) {
            #pragma unroll
            for (int j = 0; j < 12; ++j) ysp[j] = 0.f;
        } else {
            float x0 = g_SYN2[0 * TPAD + TOFF + t - 1].x + ths[0];
            ysp[0] = sigmoidf_(x0) * ws[0];
            #pragma unroll
            for (int j = 1; j < 12; ++j) ysp[j] = xno[j][h - 1] * ws[j];
        }
        float* o = sout + tid * 35;
        #pragma unroll
        for (int i = 0; i < 12; ++i) {
            float xs = g_SYN2[i * TPAD + TOFF + t].x + ths[i];
            #pragma unroll
            for (int j = 0; j < i; ++j) xs = fmaf(cds[i * 12 + j], ysp[j], xs);
            float sg  = sigmoidf_(xs);
            float xti = xno[i][h];
            o[i]      = (i == 0) ? sg * ws[0] : xti * ws[i];
            o[12 + i] = xti * wns[i];
            if (i >= 1) o[24 + i - 1] = sg;
        }
    }
    __syncthreads();
    float* ob = out + (size_t)t0 * 35;
    for (int i = tid; i < 5600; i += 192) ob[i] = sout[i];
}

// ---------------- launch ----------------
extern "C" void kernel_launch(void* const* d_in, const int* in_sizes, int n_in,
                              void* d_out, int out_size) {
    const float* S_e      = (const float*)d_in[0];
    const float* S_i      = (const float*)d_in[1];
    const float* C_syn_e  = (const float*)d_in[2];
    const float* C_syn_i  = (const float*)d_in[3];
    const float* C_den    = (const float*)d_in[4];
    const float* W_s_syn  = (const float*)d_in[5];
    const float* W_ns_syn = (const float*)d_in[6];
    const float* D_s      = (const float*)d_in[7];
    const float* D_ns     = (const float*)d_in[8];
    const float* Theta_s  = (const float*)d_in[9];
    const float* Theta_ns = (const float*)d_in[10];
    const float* W_s_sub  = (const float*)d_in[11];
    const float* W_ns_sub = (const float*)d_in[12];
    float* out = (float*)d_out;

    k0a<<<4, 256>>>(C_syn_e, C_syn_i);
    k1f<<<2534, 256>>>((const float4*)S_e, (const float4*)S_i,
                       W_s_syn, W_ns_syn, D_s, D_ns);
    k3_conv<<<125, 768>>>();
    k4_scan<<<125, 192>>>(C_den, Theta_s, Theta_ns, W_s_sub, W_ns_sub, out);
}